// round 14
// baseline (speedup 1.0000x reference)
#include <cuda_runtime.h>
#include <cuda_bf16.h>
#include <cstdint>

#define NUM 16
#define DIM 128
#define NN (NUM*DIM)            // 2048
#define BATCH 4096
#define INC 512
#define OUTC 512
#define STEPS 10
#define KP 4096                 // physical K, step chain: [Thi|Tlo] / [Rhi|Rlo]
#define KPF 1024                // physical K, final: [Ihi|Ilo] / [Ghi|Glo]
#define KSPLIT 8
#define BK 64
#define NSTAGE 5
#define RSW 36                  // smem row stride in words (32 data + 4 pad)
#define STG_W (128*RSW*2)       // words per stage (A+B) = 9216
#define SMEM_BYTES (NSTAGE*STG_W*4)   // 184320

// ---------------- device scratch ----------------
__device__ __align__(16) __nv_bfloat16 g_Text[NN*KP];        // [Thi|Tlo], 16.8MB
__device__ __align__(16) __nv_bfloat16 g_Rt[2][DIM*KP];      // [Rhi|Rlo] transposed
__device__ __align__(16) float g_P[KSPLIT*NN*DIM];           // split-K partials, 8.4MB
__device__ __align__(16) float g_S[NN*DIM];
__device__ __align__(16) float g_Rf[NN*DIM];
__device__ __align__(16) __nv_bfloat16 g_Iext[BATCH*KPF];    // [Ihi|Ilo], 8.4MB
__device__ __align__(16) __nv_bfloat16 g_Gext[OUTC*KPF];     // rows q: [Ghi|Glo] over p
__device__ __align__(16) float g_beta[NN];
__device__ __align__(16) float g_h[DIM];
__device__ __align__(16) float g_WpostT[DIM*OUTC];
__device__ __align__(16) float g_T1[DIM*OUTC];
__device__ __align__(16) float g_G[INC*OUTC];
__device__ __align__(16) float g_dvec[OUTC];
__device__ int g_ctr[STEPS*NUM];                             // split-K arrival counters

// ---------------- helpers ----------------
__device__ __forceinline__ void mma16816(float* d, const uint32_t* a, uint32_t b0, uint32_t b1) {
    asm volatile(
        "mma.sync.aligned.m16n8k16.row.col.f32.bf16.bf16.f32 "
        "{%0,%1,%2,%3}, {%4,%5,%6,%7}, {%8,%9}, {%0,%1,%2,%3};"
        : "+f"(d[0]), "+f"(d[1]), "+f"(d[2]), "+f"(d[3])
        : "r"(a[0]), "r"(a[1]), "r"(a[2]), "r"(a[3]), "r"(b0), "r"(b1));
}
__device__ __forceinline__ void ldsm4(uint32_t* r, uint32_t addr) {
    asm volatile("ldmatrix.sync.aligned.m8n8.x4.shared.b16 {%0,%1,%2,%3}, [%4];"
                 : "=r"(r[0]), "=r"(r[1]), "=r"(r[2]), "=r"(r[3]) : "r"(addr));
}
__device__ __forceinline__ void cpa16(uint32_t saddr, const void* g) {
    asm volatile("cp.async.ca.shared.global [%0], [%1], 16;" :: "r"(saddr), "l"(g));
}
__device__ __forceinline__ void cpa_commit() { asm volatile("cp.async.commit_group;" ::: "memory"); }
template<int N> __device__ __forceinline__ void cpa_wait() {
    asm volatile("cp.async.wait_group %0;" :: "n"(N) : "memory");
}
__device__ __forceinline__ uint32_t smem_u32(const void* p) {
    uint32_t a;
    asm("{ .reg .u64 t; cvta.to.shared.u64 t, %1; cvt.u32.u64 %0, t; }" : "=r"(a) : "l"(p));
    return a;
}

// ---------------- GEMM body (R13-passing): Out[128,128] = A[128,K] @ B[128,K]^T ----------
template<int SEGC, bool BIAS>
__device__ __forceinline__ void gemm_cp(const __nv_bfloat16* __restrict__ Ag, long ldA,
                                        const __nv_bfloat16* __restrict__ Bg, long ldB,
                                        int vcBase, int nch,
                                        float* __restrict__ Out, long ldo,
                                        const float* __restrict__ bias) {
    extern __shared__ __align__(16) uint32_t sm[];
    const uint32_t sbase = smem_u32(sm);
    const int tid = threadIdx.x, wid = tid >> 5, lane = tid & 31;
    const int g = lane >> 2, tc = lane & 3;
    const int wr0 = (wid & 3) * 32, wc0 = (wid >> 2) * 32;

    float acc[2][4][4];
#pragma unroll
    for (int f = 0; f < 2; f++)
#pragma unroll
        for (int nf = 0; nf < 4; nf++)
#pragma unroll
            for (int v = 0; v < 4; v++) acc[f][nf][v] = 0.f;

    const int q = lane >> 3, r8 = lane & 7;
    uint32_t aB[2], bB[2];
#pragma unroll
    for (int f = 0; f < 2; f++)
        aB[f] = (uint32_t)(((wr0 + f*16 + r8 + (q & 1)*8)*RSW + (q >> 1)*4) * 4);
#pragma unroll
    for (int n4 = 0; n4 < 2; n4++)
        bB[n4] = (uint32_t)(((128 + wc0 + n4*16 + r8 + (q >> 1)*8)*RSW + (q & 1)*4) * 4);

    const int isB = tid >= 256, lt = tid & 255;
    const int Lr = lt >> 1, offw = (lt & 1)*16;
    const __nv_bfloat16* __restrict__ Gsrc = isB ? Bg : Ag;
    const long ldS = isB ? ldB : ldA;
    const uint32_t dBase = sbase + (uint32_t)(((isB ? 128*RSW : 0) + Lr*RSW + offw) * 4);

    auto load_stage = [&](int c, int s) {
        int vc = vcBase + c;
        int m = vc & (SEGC - 1);
        int ac = (vc < 2*SEGC) ? m : SEGC + m;
        int bc = (vc < SEGC) ? vc : ((vc < 2*SEGC) ? SEGC + m : m);
        int ci = isB ? bc : ac;
        const __nv_bfloat16* gp = Gsrc + (long)Lr*ldS + (long)ci*BK + offw*2;
        uint32_t d = dBase + (uint32_t)(s*STG_W*4);
        cpa16(d, gp); cpa16(d + 16, gp + 8);
        cpa16(d + 32, gp + 16); cpa16(d + 48, gp + 24);
        cpa_commit();
    };

    int ls = 0;
#pragma unroll
    for (int p = 0; p < NSTAGE - 1; p++) {
        load_stage(p, ls);
        if (++ls == NSTAGE) ls = 0;
    }

    uint32_t af[2][2][4], bf[2][2][4];

#define LD_FR(kk, buf, stg) do {                                                  \
        uint32_t _kw = (uint32_t)((kk)*32);                                       \
        ldsm4(af[buf][0], (stg) + aB[0] + _kw);                                   \
        ldsm4(af[buf][1], (stg) + aB[1] + _kw);                                   \
        ldsm4(bf[buf][0], (stg) + bB[0] + _kw);                                   \
        ldsm4(bf[buf][1], (stg) + bB[1] + _kw);                                   \
    } while (0)

#define DO_MMA(buf) do {                                                          \
        _Pragma("unroll")                                                         \
        for (int n4 = 0; n4 < 2; n4++) {                                          \
            mma16816(acc[0][n4*2],     af[buf][0], bf[buf][n4][0], bf[buf][n4][1]); \
            mma16816(acc[1][n4*2],     af[buf][1], bf[buf][n4][0], bf[buf][n4][1]); \
            mma16816(acc[0][n4*2 + 1], af[buf][0], bf[buf][n4][2], bf[buf][n4][3]); \
            mma16816(acc[1][n4*2 + 1], af[buf][1], bf[buf][n4][2], bf[buf][n4][3]); \
        }                                                                         \
    } while (0)

    int cs = 0;
    for (int ch = 0; ch < nch; ch++) {
        const int rem = nch - 1 - ch;
        if (rem >= 3) cpa_wait<3>();
        else if (rem == 2) cpa_wait<2>();
        else if (rem == 1) cpa_wait<1>();
        else cpa_wait<0>();
        __syncthreads();
        if (ch + NSTAGE - 1 < nch) {
            load_stage(ch + NSTAGE - 1, ls);
            if (++ls == NSTAGE) ls = 0;
        }
        const uint32_t stg = sbase + (uint32_t)(cs*STG_W*4);
        if (++cs == NSTAGE) cs = 0;
        LD_FR(0, 0, stg);
        LD_FR(1, 1, stg);
        DO_MMA(0);
        LD_FR(2, 0, stg);
        DO_MMA(1);
        LD_FR(3, 1, stg);
        DO_MMA(0);
        DO_MMA(1);
    }
#undef LD_FR
#undef DO_MMA
#pragma unroll
    for (int f = 0; f < 2; f++) {
        const int row0 = wr0 + f*16 + g;
#pragma unroll
        for (int nf = 0; nf < 4; nf++) {
            const int col = wc0 + nf*8 + tc*2;
            float2 v0 = make_float2(acc[f][nf][0], acc[f][nf][1]);
            float2 v1 = make_float2(acc[f][nf][2], acc[f][nf][3]);
            if (BIAS) {
                float2 d = *(const float2*)&bias[col];
                v0.x += d.x; v0.y += d.y; v1.x += d.x; v1.y += d.y;
            }
            *(float2*)(Out + (long)row0*ldo + col)       = v0;
            *(float2*)(Out + (long)(row0 + 8)*ldo + col) = v1;
        }
    }
}

// step MMA with FUSED split-K reduction (last CTA per mtile reduces)
__global__ void __launch_bounds__(512, 1) k_mma_step(int cur, int s) {
    extern __shared__ __align__(16) uint32_t sm[];
    const int ks = blockIdx.x, mt = blockIdx.y;
    const int tid = threadIdx.x;
    gemm_cp<32, false>(g_Text + (size_t)mt*128*KP, KP,
                       g_Rt[cur], KP,
                       ks*12, 12,
                       g_P + ((size_t)ks*NN + mt*128)*DIM, DIM, nullptr);

    // ---- fused reduction: last-arriving CTA of this mtile reduces all 8 partials ----
    __threadfence();
    __shared__ int isLast;
    __syncthreads();               // all P stores of this CTA issued before the fence above
    if (tid == 0) {
        int done = atomicAdd(&g_ctr[s*NUM + mt], 1);
        isLast = (done == KSPLIT - 1);
    }
    __syncthreads();
    if (!isLast) return;
    __threadfence();               // acquire: other CTAs' fenced P writes now visible

    float* slab = (float*)sm;      // [128][129] floats = 66 KB (fits in 184 KB dyn smem)
    const int addS = (s < STEPS - 1);
    for (int u = tid; u < 128*128; u += 512) {
        int rr = u >> 7, e = u & 127;
        float v = 0.f;
#pragma unroll
        for (int k = 0; k < KSPLIT; k++)
            v += g_P[(size_t)k*NN*DIM + (size_t)(mt*128 + rr)*DIM + e];
        g_Rf[(size_t)(mt*128 + rr)*DIM + e] = v;
        if (addS) g_S[(size_t)(mt*128 + rr)*DIM + e] += v;
        slab[rr*129 + e] = v;
    }
    if (s == STEPS - 1) return;    // no Rt needed after last step
    __syncthreads();
    const int e = tid >> 2, c32 = (tid & 3) * 32;
    __nv_bfloat16* Rt = g_Rt[cur ^ 1];
#pragma unroll
    for (int g8 = 0; g8 < 4; g8++) {
        const int rr0 = c32 + g8*8;
        uint32_t hw[4], lw[4];
#pragma unroll
        for (int c2 = 0; c2 < 4; c2++) {
            float v0 = slab[(rr0 + 2*c2)*129 + e];
            float v1 = slab[(rr0 + 2*c2 + 1)*129 + e];
            __nv_bfloat16 h0 = __float2bfloat16(v0);
            __nv_bfloat16 h1 = __float2bfloat16(v1);
            __nv_bfloat162 hh; hh.x = h0; hh.y = h1;
            hw[c2] = *(uint32_t*)&hh;
            __nv_bfloat162 ll;
            ll.x = __float2bfloat16(v0 - __bfloat162float(h0));
            ll.y = __float2bfloat16(v1 - __bfloat162float(h1));
            lw[c2] = *(uint32_t*)&ll;
        }
        *(uint4*)&Rt[(size_t)e*KP + mt*128 + rr0]        = make_uint4(hw[0], hw[1], hw[2], hw[3]);
        *(uint4*)&Rt[(size_t)e*KP + 2048 + mt*128 + rr0] = make_uint4(lw[0], lw[1], lw[2], lw[3]);
    }
}

// final MMA: virtual K=1536; bias fused
__global__ void __launch_bounds__(512, 1) k_mma_fin(float* __restrict__ out) {
    const int qt = blockIdx.x, bt = blockIdx.y;
    gemm_cp<8, true>(g_Iext + (size_t)bt*128*KPF, KPF,
                     g_Gext + (size_t)qt*128*KPF, KPF,
                     0, 24,
                     out + (size_t)bt*128*OUTC + qt*128, OUTC, g_dvec + qt*128);
}

// ---------------- prep kernels ----------------

__global__ void k_prep(const float* __restrict__ life, const float* __restrict__ bl) {
    int j = blockIdx.x, g = threadIdx.x;
    float s = 0.f;
#pragma unroll
    for (int i = 0; i < NUM; i++) {
        float gt = fmaxf(life[i*NUM + j], 0.f);
        s += gt * bl[(i*NUM + j)*DIM + g];
    }
    g_beta[j*DIM + g] = s;
}

// T phys [Thi|Tlo] of gate*W
__global__ void k_make_T(const float* __restrict__ W, const float* __restrict__ life) {
    const int j = blockIdx.x, i = blockIdx.y;
    const float gate = fmaxf(life[i*NUM + j], 0.f);
    const float* __restrict__ Wb = W + (size_t)(i*NUM + j)*DIM*DIM;   // [g][f]
    __shared__ float sm[32][DIM + 1];
    const int tid = threadIdx.x;
    for (int g0 = 0; g0 < DIM; g0 += 32) {
        for (int u = tid; u < 32*DIM; u += 256) {
            int gg = u >> 7, f = u & 127;
            sm[gg][f] = Wb[(size_t)(g0 + gg)*DIM + f];
        }
        __syncthreads();
#pragma unroll
        for (int it = 0; it < 8; it++) {
            int pi = it*256 + tid;
            int f = pi >> 4, gp = (pi & 15) * 2;
            float x0 = gate * sm[gp][f];
            float x1 = gate * sm[gp + 1][f];
            __nv_bfloat16 h0 = __float2bfloat16(x0);
            __nv_bfloat16 h1 = __float2bfloat16(x1);
            __nv_bfloat162 hv; hv.x = h0; hv.y = h1;
            __nv_bfloat162 lv;
            lv.x = __float2bfloat16(x0 - __bfloat162float(h0));
            lv.y = __float2bfloat16(x1 - __bfloat162float(h1));
            size_t row = (size_t)(i*DIM + f)*KP;
            int col = j*DIM + g0 + gp;
            *(__nv_bfloat162*)&g_Text[row + col]        = hv;
            *(__nv_bfloat162*)&g_Text[row + 2048 + col] = lv;
        }
        __syncthreads();
    }
}

// Rt[0] phys: [Rhi identity | Rlo = 0]; S = R_0; zero split-K counters
__global__ void k_initRS() {
    int r = blockIdx.x, e = threadIdx.x;     // grid 2048 x 128
    g_S[(size_t)r*DIM + e] = (r == (NN - DIM) + e) ? 1.f : 0.f;
    if (e == 0 && r < STEPS*NUM) g_ctr[r] = 0;
    if (r < DIM) {
#pragma unroll
        for (int it = 0; it < 16; it++) {
            int cp = (it*128 + e) * 2;       // col pair over KP=4096
            float v0 = (cp < 2048 && cp     == (NN - DIM) + r) ? 1.f : 0.f;
            float v1 = (cp < 2048 && cp + 1 == (NN - DIM) + r) ? 1.f : 0.f;
            __nv_bfloat162 v; v.x = __float2bfloat16(v0); v.y = __float2bfloat16(v1);
            *(__nv_bfloat162*)&g_Rt[0][(size_t)r*KP + cp] = v;
        }
    }
}

// ---------------- merged combine kernels (R13-passing) ----------------
__global__ void k_combo1(const float* __restrict__ Wpost, const float* __restrict__ bpre) {
    const int tid = threadIdx.x;                       // 512
    if (blockIdx.x < DIM) {
        int e = blockIdx.x;
        g_WpostT[e*OUTC + tid] = Wpost[(size_t)tid*DIM + e];
    } else {
        int e = blockIdx.x - DIM;
        float s = 0.f;
        for (int r = tid; r < NN; r += 512) s += g_beta[r] * g_S[(size_t)r*DIM + e];
        if (tid < DIM) s += bpre[tid] * g_Rf[(size_t)tid*DIM + e];
        __shared__ float red[512];
        red[tid] = s;
        __syncthreads();
        for (int off = 256; off > 0; off >>= 1) {
            if (tid < off) red[tid] += red[tid + off];
            __syncthreads();
        }
        if (tid == 0) g_h[e] = red[0];
    }
}

__global__ void k_combo2(const float* __restrict__ bpost) {
    const int tid = threadIdx.x;                       // 128
    if (blockIdx.x < 512) {
        int d = blockIdx.x >> 2;
        int q = (blockIdx.x & 3)*128 + tid;
        const float* __restrict__ Er = g_Rf + (size_t)d*DIM;
        float acc = 0.f;
#pragma unroll 8
        for (int e = 0; e < DIM; e++) acc += Er[e] * g_WpostT[e*OUTC + q];
        g_T1[d*OUTC + q] = acc;
    } else {
        int q = (blockIdx.x - 512)*128 + tid;
        float acc = bpost[q];
#pragma unroll 8
        for (int e = 0; e < DIM; e++) acc += g_h[e] * g_WpostT[e*OUTC + q];
        g_dvec[q] = acc;
    }
}

__global__ void k_G(const float* __restrict__ Wpre) {
    int p = blockIdx.y;
    int q = blockIdx.x*128 + threadIdx.x;
    float acc = 0.f;
#pragma unroll 8
    for (int d = 0; d < DIM; d++) acc += Wpre[d*INC + p] * g_T1[d*OUTC + q];
    g_G[p*OUTC + q] = acc;
}

// inp -> phys [Ihi|Ilo]
__global__ void k_split_inp(const float* __restrict__ inp) {
    int b = blockIdx.x, tid = threadIdx.x;
#pragma unroll
    for (int it = 0; it < 2; it++) {
        int qp = (it*128 + tid) * 2;
        float2 x = *(const float2*)&inp[(size_t)b*INC + qp];
        __nv_bfloat16 h0 = __float2bfloat16(x.x);
        __nv_bfloat16 h1 = __float2bfloat16(x.y);
        __nv_bfloat162 hv; hv.x = h0; hv.y = h1;
        __nv_bfloat162 lv;
        lv.x = __float2bfloat16(x.x - __bfloat162float(h0));
        lv.y = __float2bfloat16(x.y - __bfloat162float(h1));
        size_t ro = (size_t)b*KPF;
        *(__nv_bfloat162*)&g_Iext[ro + qp]       = hv;
        *(__nv_bfloat162*)&g_Iext[ro + 512 + qp] = lv;
    }
}

// Gext row q over p: phys [Ghi|Glo] of G[p][q]
__global__ void k_split_G() {
    int q = blockIdx.x;
    for (int p = threadIdx.x; p < INC; p += 128) {
        float x = g_G[(size_t)p*OUTC + q];
        __nv_bfloat16 h = __float2bfloat16(x);
        __nv_bfloat16 l = __float2bfloat16(x - __bfloat162float(h));
        size_t ro = (size_t)q*KPF;
        g_Gext[ro + p]       = h;
        g_Gext[ro + 512 + p] = l;
    }
}

// ---------------- launch ----------------
extern "C" void kernel_launch(void* const* d_in, const int* in_sizes, int n_in,
                              void* d_out, int out_size) {
    (void)in_sizes; (void)n_in; (void)out_size;
    const float* inp   = (const float*)d_in[0];
    const float* Wpre  = (const float*)d_in[1];
    const float* bpre  = (const float*)d_in[2];
    const float* W     = (const float*)d_in[3];
    const float* bl    = (const float*)d_in[4];
    const float* life  = (const float*)d_in[5];
    const float* Wpost = (const float*)d_in[6];
    const float* bpost = (const float*)d_in[7];
    float* out = (float*)d_out;

    cudaFuncSetAttribute(k_mma_step, cudaFuncAttributeMaxDynamicSharedMemorySize, SMEM_BYTES);
    cudaFuncSetAttribute(k_mma_fin,  cudaFuncAttributeMaxDynamicSharedMemorySize, SMEM_BYTES);

    k_make_T<<<dim3(NUM, NUM), 256>>>(W, life);          // idx 0
    k_initRS<<<NN, DIM>>>();                             // idx 1
    k_prep<<<NUM, DIM>>>(life, bl);                      // idx 2

    int cur = 0;
    for (int s = 0; s < STEPS; s++) {
        k_mma_step<<<dim3(KSPLIT, NUM), 512, SMEM_BYTES>>>(cur, s);  // idx 3.. (profiled 5)
        cur ^= 1;
    }

    k_combo1<<<2*DIM, 512>>>(Wpost, bpre);
    k_combo2<<<516, 128>>>(bpost);
    k_G<<<dim3(OUTC/128, INC), 128>>>(Wpre);
    k_split_inp<<<BATCH, 128>>>(inp);
    k_split_G<<<OUTC, 128>>>();
    k_mma_fin<<<dim3(OUTC/128, BATCH/128), 512, SMEM_BYTES>>>(out);
}

// round 15
// speedup vs baseline: 1.3329x; 1.3329x over previous
#include <cuda_runtime.h>
#include <cuda_bf16.h>
#include <cstdint>

#define NUM 16
#define DIM 128
#define NN (NUM*DIM)            // 2048
#define BATCH 4096
#define INC 512
#define OUTC 512
#define STEPS 10
#define KP 4096                 // physical K, step chain: [Thi|Tlo] / [Rhi|Rlo]
#define KPF 1024                // physical K, final: [Ihi|Ilo] / [Ghi|Glo]
#define KSPLIT 8
#define BK 64
#define NSTAGE 5
#define RSW 36                  // smem row stride in words (32 data + 4 pad)
#define STG_W (128*RSW*2)       // words per stage (A+B) = 9216
#define SMEM_BYTES (NSTAGE*STG_W*4)   // 184320
#define NCTA (KSPLIT*NUM)       // 128 persistent CTAs

// ---------------- device scratch ----------------
__device__ __align__(16) __nv_bfloat16 g_Text[NN*KP];        // [Thi|Tlo], 16.8MB
__device__ __align__(16) __nv_bfloat16 g_Rt[2][DIM*KP];      // [Rhi|Rlo] transposed
__device__ __align__(16) float g_P[KSPLIT*NN*DIM];           // split-K partials, 8.4MB
__device__ __align__(16) float g_S[NN*DIM];
__device__ __align__(16) float g_Rf[NN*DIM];
__device__ __align__(16) __nv_bfloat16 g_Iext[BATCH*KPF];    // [Ihi|Ilo], 8.4MB
__device__ __align__(16) __nv_bfloat16 g_Gext[OUTC*KPF];     // rows q: [Ghi|Glo] over p
__device__ __align__(16) float g_beta[NN];
__device__ __align__(16) float g_h[DIM];
__device__ __align__(16) float g_WpostT[DIM*OUTC];
__device__ __align__(16) float g_T1[DIM*OUTC];
__device__ __align__(16) float g_G[INC*OUTC];
__device__ __align__(16) float g_dvec[OUTC];
__device__ int g_bar;                                        // grid barrier counter

// ---------------- helpers ----------------
__device__ __forceinline__ void mma16816(float* d, const uint32_t* a, uint32_t b0, uint32_t b1) {
    asm volatile(
        "mma.sync.aligned.m16n8k16.row.col.f32.bf16.bf16.f32 "
        "{%0,%1,%2,%3}, {%4,%5,%6,%7}, {%8,%9}, {%0,%1,%2,%3};"
        : "+f"(d[0]), "+f"(d[1]), "+f"(d[2]), "+f"(d[3])
        : "r"(a[0]), "r"(a[1]), "r"(a[2]), "r"(a[3]), "r"(b0), "r"(b1));
}
__device__ __forceinline__ void ldsm4(uint32_t* r, uint32_t addr) {
    asm volatile("ldmatrix.sync.aligned.m8n8.x4.shared.b16 {%0,%1,%2,%3}, [%4];"
                 : "=r"(r[0]), "=r"(r[1]), "=r"(r[2]), "=r"(r[3]) : "r"(addr));
}
__device__ __forceinline__ void cpa16(uint32_t saddr, const void* g) {
    asm volatile("cp.async.ca.shared.global [%0], [%1], 16;" :: "r"(saddr), "l"(g));
}
__device__ __forceinline__ void cpa_commit() { asm volatile("cp.async.commit_group;" ::: "memory"); }
template<int N> __device__ __forceinline__ void cpa_wait() {
    asm volatile("cp.async.wait_group %0;" :: "n"(N) : "memory");
}
__device__ __forceinline__ uint32_t smem_u32(const void* p) {
    uint32_t a;
    asm("{ .reg .u64 t; cvta.to.shared.u64 t, %1; cvt.u32.u64 %0, t; }" : "=r"(a) : "l"(p));
    return a;
}
// grid-wide barrier (all NCTA CTAs resident; R14-validated fence/atomic pattern)
__device__ __forceinline__ void grid_bar(int target) {
    __threadfence();
    __syncthreads();
    if (threadIdx.x == 0) {
        atomicAdd(&g_bar, 1);
        while (atomicAdd(&g_bar, 0) < target) __nanosleep(64);
    }
    __syncthreads();
    __threadfence();
}

// ---------------- GEMM body (R13-passing): Out[128,128] = A[128,K] @ B[128,K]^T ----------
template<int SEGC, bool BIAS>
__device__ __forceinline__ void gemm_cp(const __nv_bfloat16* __restrict__ Ag, long ldA,
                                        const __nv_bfloat16* __restrict__ Bg, long ldB,
                                        int vcBase, int nch,
                                        float* __restrict__ Out, long ldo,
                                        const float* __restrict__ bias) {
    extern __shared__ __align__(16) uint32_t sm[];
    const uint32_t sbase = smem_u32(sm);
    const int tid = threadIdx.x, wid = tid >> 5, lane = tid & 31;
    const int g = lane >> 2, tc = lane & 3;
    const int wr0 = (wid & 3) * 32, wc0 = (wid >> 2) * 32;

    float acc[2][4][4];
#pragma unroll
    for (int f = 0; f < 2; f++)
#pragma unroll
        for (int nf = 0; nf < 4; nf++)
#pragma unroll
            for (int v = 0; v < 4; v++) acc[f][nf][v] = 0.f;

    const int q = lane >> 3, r8 = lane & 7;
    uint32_t aB[2], bB[2];
#pragma unroll
    for (int f = 0; f < 2; f++)
        aB[f] = (uint32_t)(((wr0 + f*16 + r8 + (q & 1)*8)*RSW + (q >> 1)*4) * 4);
#pragma unroll
    for (int n4 = 0; n4 < 2; n4++)
        bB[n4] = (uint32_t)(((128 + wc0 + n4*16 + r8 + (q >> 1)*8)*RSW + (q & 1)*4) * 4);

    const int isB = tid >= 256, lt = tid & 255;
    const int Lr = lt >> 1, offw = (lt & 1)*16;
    const __nv_bfloat16* __restrict__ Gsrc = isB ? Bg : Ag;
    const long ldS = isB ? ldB : ldA;
    const uint32_t dBase = sbase + (uint32_t)(((isB ? 128*RSW : 0) + Lr*RSW + offw) * 4);

    auto load_stage = [&](int c, int s) {
        int vc = vcBase + c;
        int m = vc & (SEGC - 1);
        int ac = (vc < 2*SEGC) ? m : SEGC + m;
        int bc = (vc < SEGC) ? vc : ((vc < 2*SEGC) ? SEGC + m : m);
        int ci = isB ? bc : ac;
        const __nv_bfloat16* gp = Gsrc + (long)Lr*ldS + (long)ci*BK + offw*2;
        uint32_t d = dBase + (uint32_t)(s*STG_W*4);
        cpa16(d, gp); cpa16(d + 16, gp + 8);
        cpa16(d + 32, gp + 16); cpa16(d + 48, gp + 24);
        cpa_commit();
    };

    int ls = 0;
#pragma unroll
    for (int p = 0; p < NSTAGE - 1; p++) {
        load_stage(p, ls);
        if (++ls == NSTAGE) ls = 0;
    }

    uint32_t af[2][2][4], bf[2][2][4];

#define LD_FR(kk, buf, stg) do {                                                  \
        uint32_t _kw = (uint32_t)((kk)*32);                                       \
        ldsm4(af[buf][0], (stg) + aB[0] + _kw);                                   \
        ldsm4(af[buf][1], (stg) + aB[1] + _kw);                                   \
        ldsm4(bf[buf][0], (stg) + bB[0] + _kw);                                   \
        ldsm4(bf[buf][1], (stg) + bB[1] + _kw);                                   \
    } while (0)

#define DO_MMA(buf) do {                                                          \
        _Pragma("unroll")                                                         \
        for (int n4 = 0; n4 < 2; n4++) {                                          \
            mma16816(acc[0][n4*2],     af[buf][0], bf[buf][n4][0], bf[buf][n4][1]); \
            mma16816(acc[1][n4*2],     af[buf][1], bf[buf][n4][0], bf[buf][n4][1]); \
            mma16816(acc[0][n4*2 + 1], af[buf][0], bf[buf][n4][2], bf[buf][n4][3]); \
            mma16816(acc[1][n4*2 + 1], af[buf][1], bf[buf][n4][2], bf[buf][n4][3]); \
        }                                                                         \
    } while (0)

    int cs = 0;
    for (int ch = 0; ch < nch; ch++) {
        const int rem = nch - 1 - ch;
        if (rem >= 3) cpa_wait<3>();
        else if (rem == 2) cpa_wait<2>();
        else if (rem == 1) cpa_wait<1>();
        else cpa_wait<0>();
        __syncthreads();
        if (ch + NSTAGE - 1 < nch) {
            load_stage(ch + NSTAGE - 1, ls);
            if (++ls == NSTAGE) ls = 0;
        }
        const uint32_t stg = sbase + (uint32_t)(cs*STG_W*4);
        if (++cs == NSTAGE) cs = 0;
        LD_FR(0, 0, stg);
        LD_FR(1, 1, stg);
        DO_MMA(0);
        LD_FR(2, 0, stg);
        DO_MMA(1);
        LD_FR(3, 1, stg);
        DO_MMA(0);
        DO_MMA(1);
    }
#undef LD_FR
#undef DO_MMA
#pragma unroll
    for (int f = 0; f < 2; f++) {
        const int row0 = wr0 + f*16 + g;
#pragma unroll
        for (int nf = 0; nf < 4; nf++) {
            const int col = wc0 + nf*8 + tc*2;
            float2 v0 = make_float2(acc[f][nf][0], acc[f][nf][1]);
            float2 v1 = make_float2(acc[f][nf][2], acc[f][nf][3]);
            if (BIAS) {
                float2 d = *(const float2*)&bias[col];
                v0.x += d.x; v0.y += d.y; v1.x += d.x; v1.y += d.y;
            }
            *(float2*)(Out + (long)row0*ldo + col)       = v0;
            *(float2*)(Out + (long)(row0 + 8)*ldo + col) = v1;
        }
    }
}

// ---------------- persistent step kernel: all 10 steps, grid barrier, distributed reduce ----
__global__ void __launch_bounds__(512, 1) k_step_all() {
    extern __shared__ __align__(16) uint32_t sm[];
    const int ks = blockIdx.x, mt = blockIdx.y;
    const int lin = mt*KSPLIT + ks;                 // 0..127
    const int tid = threadIdx.x;
    float* slab = (float*)sm;                       // [16][129] floats after gemm

    int cur = 0, phase = 0;
    for (int s = 0; s < STEPS; s++) {
        gemm_cp<32, false>(g_Text + (size_t)mt*128*KP, KP,
                           g_Rt[cur], KP,
                           ks*12, 12,
                           g_P + ((size_t)ks*NN + mt*128)*DIM, DIM, nullptr);
        grid_bar(++phase * NCTA);

        // distributed reduce: this CTA owns rows [lin*16, lin*16+16)
        const int row0 = lin*16;
        const int addS = (s < STEPS - 1);
        for (int u = tid; u < 16*DIM; u += 512) {
            int rr = u >> 7, e = u & 127;
            float v = 0.f;
#pragma unroll
            for (int k = 0; k < KSPLIT; k++)
                v += g_P[(size_t)k*NN*DIM + (size_t)(row0 + rr)*DIM + e];
            g_Rf[(size_t)(row0 + rr)*DIM + e] = v;
            if (addS) g_S[(size_t)(row0 + rr)*DIM + e] += v;
            slab[rr*129 + e] = v;
        }
        if (s == STEPS - 1) break;                   // no Rt needed after last step
        __syncthreads();
        {
            const int e = tid >> 2, c4 = (tid & 3) * 4;
            __nv_bfloat16* Rt = g_Rt[cur ^ 1];
            uint32_t hw[2], lw[2];
#pragma unroll
            for (int c2 = 0; c2 < 2; c2++) {
                float v0 = slab[(c4 + 2*c2)*129 + e];
                float v1 = slab[(c4 + 2*c2 + 1)*129 + e];
                __nv_bfloat16 h0 = __float2bfloat16(v0);
                __nv_bfloat16 h1 = __float2bfloat16(v1);
                __nv_bfloat162 hh; hh.x = h0; hh.y = h1;
                hw[c2] = *(uint32_t*)&hh;
                __nv_bfloat162 ll;
                ll.x = __float2bfloat16(v0 - __bfloat162float(h0));
                ll.y = __float2bfloat16(v1 - __bfloat162float(h1));
                lw[c2] = *(uint32_t*)&ll;
            }
            *(uint2*)&Rt[(size_t)e*KP + row0 + c4]        = make_uint2(hw[0], hw[1]);
            *(uint2*)&Rt[(size_t)e*KP + 2048 + row0 + c4] = make_uint2(lw[0], lw[1]);
        }
        grid_bar(++phase * NCTA);
        cur ^= 1;
    }
}

// final MMA: virtual K=1536; bias fused
__global__ void __launch_bounds__(512, 1) k_mma_fin(float* __restrict__ out) {
    const int qt = blockIdx.x, bt = blockIdx.y;
    gemm_cp<8, true>(g_Iext + (size_t)bt*128*KPF, KPF,
                     g_Gext + (size_t)qt*128*KPF, KPF,
                     0, 24,
                     out + (size_t)bt*128*OUTC + qt*128, OUTC, g_dvec + qt*128);
}

// ---------------- prep kernels ----------------

__global__ void k_prep(const float* __restrict__ life, const float* __restrict__ bl) {
    int j = blockIdx.x, g = threadIdx.x;
    float s = 0.f;
#pragma unroll
    for (int i = 0; i < NUM; i++) {
        float gt = fmaxf(life[i*NUM + j], 0.f);
        s += gt * bl[(i*NUM + j)*DIM + g];
    }
    g_beta[j*DIM + g] = s;
}

// T phys [Thi|Tlo] of gate*W
__global__ void k_make_T(const float* __restrict__ W, const float* __restrict__ life) {
    const int j = blockIdx.x, i = blockIdx.y;
    const float gate = fmaxf(life[i*NUM + j], 0.f);
    const float* __restrict__ Wb = W + (size_t)(i*NUM + j)*DIM*DIM;   // [g][f]
    __shared__ float sm[32][DIM + 1];
    const int tid = threadIdx.x;
    for (int g0 = 0; g0 < DIM; g0 += 32) {
        for (int u = tid; u < 32*DIM; u += 256) {
            int gg = u >> 7, f = u & 127;
            sm[gg][f] = Wb[(size_t)(g0 + gg)*DIM + f];
        }
        __syncthreads();
#pragma unroll
        for (int it = 0; it < 8; it++) {
            int pi = it*256 + tid;
            int f = pi >> 4, gp = (pi & 15) * 2;
            float x0 = gate * sm[gp][f];
            float x1 = gate * sm[gp + 1][f];
            __nv_bfloat16 h0 = __float2bfloat16(x0);
            __nv_bfloat16 h1 = __float2bfloat16(x1);
            __nv_bfloat162 hv; hv.x = h0; hv.y = h1;
            __nv_bfloat162 lv;
            lv.x = __float2bfloat16(x0 - __bfloat162float(h0));
            lv.y = __float2bfloat16(x1 - __bfloat162float(h1));
            size_t row = (size_t)(i*DIM + f)*KP;
            int col = j*DIM + g0 + gp;
            *(__nv_bfloat162*)&g_Text[row + col]        = hv;
            *(__nv_bfloat162*)&g_Text[row + 2048 + col] = lv;
        }
        __syncthreads();
    }
}

// Rt[0] phys: [Rhi identity | Rlo = 0]; S = R_0; zero grid barrier
__global__ void k_initRS() {
    int r = blockIdx.x, e = threadIdx.x;     // grid 2048 x 128
    g_S[(size_t)r*DIM + e] = (r == (NN - DIM) + e) ? 1.f : 0.f;
    if (r == 0 && e == 0) g_bar = 0;
    if (r < DIM) {
#pragma unroll
        for (int it = 0; it < 16; it++) {
            int cp = (it*128 + e) * 2;       // col pair over KP=4096
            float v0 = (cp < 2048 && cp     == (NN - DIM) + r) ? 1.f : 0.f;
            float v1 = (cp < 2048 && cp + 1 == (NN - DIM) + r) ? 1.f : 0.f;
            __nv_bfloat162 v; v.x = __float2bfloat16(v0); v.y = __float2bfloat16(v1);
            *(__nv_bfloat162*)&g_Rt[0][(size_t)r*KP + cp] = v;
        }
    }
}

// ---------------- merged combine kernels (R13-passing) ----------------
__global__ void k_combo1(const float* __restrict__ Wpost, const float* __restrict__ bpre) {
    const int tid = threadIdx.x;                       // 512
    if (blockIdx.x < DIM) {
        int e = blockIdx.x;
        g_WpostT[e*OUTC + tid] = Wpost[(size_t)tid*DIM + e];
    } else {
        int e = blockIdx.x - DIM;
        float s = 0.f;
        for (int r = tid; r < NN; r += 512) s += g_beta[r] * g_S[(size_t)r*DIM + e];
        if (tid < DIM) s += bpre[tid] * g_Rf[(size_t)tid*DIM + e];
        __shared__ float red[512];
        red[tid] = s;
        __syncthreads();
        for (int off = 256; off > 0; off >>= 1) {
            if (tid < off) red[tid] += red[tid + off];
            __syncthreads();
        }
        if (tid == 0) g_h[e] = red[0];
    }
}

__global__ void k_combo2(const float* __restrict__ bpost) {
    const int tid = threadIdx.x;                       // 128
    if (blockIdx.x < 512) {
        int d = blockIdx.x >> 2;
        int q = (blockIdx.x & 3)*128 + tid;
        const float* __restrict__ Er = g_Rf + (size_t)d*DIM;
        float acc = 0.f;
#pragma unroll 8
        for (int e = 0; e < DIM; e++) acc += Er[e] * g_WpostT[e*OUTC + q];
        g_T1[d*OUTC + q] = acc;
    } else {
        int q = (blockIdx.x - 512)*128 + tid;
        float acc = bpost[q];
#pragma unroll 8
        for (int e = 0; e < DIM; e++) acc += g_h[e] * g_WpostT[e*OUTC + q];
        g_dvec[q] = acc;
    }
}

__global__ void k_G(const float* __restrict__ Wpre) {
    int p = blockIdx.y;
    int q = blockIdx.x*128 + threadIdx.x;
    float acc = 0.f;
#pragma unroll 8
    for (int d = 0; d < DIM; d++) acc += Wpre[d*INC + p] * g_T1[d*OUTC + q];
    g_G[p*OUTC + q] = acc;
}

// inp -> phys [Ihi|Ilo]
__global__ void k_split_inp(const float* __restrict__ inp) {
    int b = blockIdx.x, tid = threadIdx.x;
#pragma unroll
    for (int it = 0; it < 2; it++) {
        int qp = (it*128 + tid) * 2;
        float2 x = *(const float2*)&inp[(size_t)b*INC + qp];
        __nv_bfloat16 h0 = __float2bfloat16(x.x);
        __nv_bfloat16 h1 = __float2bfloat16(x.y);
        __nv_bfloat162 hv; hv.x = h0; hv.y = h1;
        __nv_bfloat162 lv;
        lv.x = __float2bfloat16(x.x - __bfloat162float(h0));
        lv.y = __float2bfloat16(x.y - __bfloat162float(h1));
        size_t ro = (size_t)b*KPF;
        *(__nv_bfloat162*)&g_Iext[ro + qp]       = hv;
        *(__nv_bfloat162*)&g_Iext[ro + 512 + qp] = lv;
    }
}

// Gext row q over p: phys [Ghi|Glo] of G[p][q]
__global__ void k_split_G() {
    int q = blockIdx.x;
    for (int p = threadIdx.x; p < INC; p += 128) {
        float x = g_G[(size_t)p*OUTC + q];
        __nv_bfloat16 h = __float2bfloat16(x);
        __nv_bfloat16 l = __float2bfloat16(x - __bfloat162float(h));
        size_t ro = (size_t)q*KPF;
        g_Gext[ro + p]       = h;
        g_Gext[ro + 512 + p] = l;
    }
}

// ---------------- launch ----------------
extern "C" void kernel_launch(void* const* d_in, const int* in_sizes, int n_in,
                              void* d_out, int out_size) {
    (void)in_sizes; (void)n_in; (void)out_size;
    const float* inp   = (const float*)d_in[0];
    const float* Wpre  = (const float*)d_in[1];
    const float* bpre  = (const float*)d_in[2];
    const float* W     = (const float*)d_in[3];
    const float* bl    = (const float*)d_in[4];
    const float* life  = (const float*)d_in[5];
    const float* Wpost = (const float*)d_in[6];
    const float* bpost = (const float*)d_in[7];
    float* out = (float*)d_out;

    cudaFuncSetAttribute(k_step_all, cudaFuncAttributeMaxDynamicSharedMemorySize, SMEM_BYTES);
    cudaFuncSetAttribute(k_mma_fin,  cudaFuncAttributeMaxDynamicSharedMemorySize, SMEM_BYTES);

    k_make_T<<<dim3(NUM, NUM), 256>>>(W, life);          // idx 0
    k_initRS<<<NN, DIM>>>();                             // idx 1
    k_prep<<<NUM, DIM>>>(life, bl);                      // idx 2

    k_step_all<<<dim3(KSPLIT, NUM), 512, SMEM_BYTES>>>();   // idx 3 — all 10 steps

    k_combo1<<<2*DIM, 512>>>(Wpost, bpre);
    k_combo2<<<516, 128>>>(bpost);
    k_G<<<dim3(OUTC/128, INC), 128>>>(Wpre);
    k_split_inp<<<BATCH, 128>>>(inp);
    k_split_G<<<OUTC, 128>>>();
    k_mma_fin<<<dim3(OUTC/128, BATCH/128), 512, SMEM_BYTES>>>(out);
}

// round 16
// speedup vs baseline: 1.4805x; 1.1107x over previous
#include <cuda_runtime.h>
#include <cuda_bf16.h>
#include <cuda_fp16.h>
#include <cstdint>

#define NUM 16
#define DIM 128
#define NN (NUM*DIM)            // 2048
#define BATCH 4096
#define INC 512
#define OUTC 512
#define STEPS 10
#define KP 4096                 // physical K, step chain: [Thi|Tlo] / [Rhi|Rlo]
#define KSPLIT 8
#define BK 64
#define NSTAGE 5
#define RSW 36                  // smem row stride in words (32 data + 4 pad)
#define STG_W (128*RSW*2)       // words per stage (A+B) = 9216
#define SMEM_BYTES (NSTAGE*STG_W*4)   // 184320
#define NCTA (KSPLIT*NUM)       // 128 persistent CTAs

// ---------------- device scratch ----------------
__device__ __align__(16) __nv_bfloat16 g_Text[NN*KP];        // [Thi|Tlo], 16.8MB
__device__ __align__(16) __nv_bfloat16 g_Rt[2][DIM*KP];      // [Rhi|Rlo] transposed
__device__ __align__(16) float g_P[KSPLIT*NN*DIM];           // split-K partials
__device__ __align__(16) float g_S[NN*DIM];
__device__ __align__(16) float g_Rf[NN*DIM];                 // final R (block 0 rows used)
__device__ __align__(16) __half g_Ifin[BATCH*1024];          // [Ihi|Ilo] fp16, 8.4MB
__device__ __align__(16) __half g_Gfin[OUTC*512];            // Ghi fp16, rows q over p
__device__ __align__(16) float g_beta[NN];
__device__ __align__(16) float g_h[DIM];
__device__ __align__(16) float g_WpostT[DIM*OUTC];
__device__ __align__(16) float g_T1[DIM*OUTC];
__device__ __align__(16) float g_G[INC*OUTC];
__device__ __align__(16) float g_dvec[OUTC];
__device__ int g_bar;                                        // grid barrier counter

// ---------------- helpers ----------------
template<bool F16>
__device__ __forceinline__ void mma_any(float* d, const uint32_t* a, uint32_t b0, uint32_t b1) {
    if (F16)
        asm volatile(
            "mma.sync.aligned.m16n8k16.row.col.f32.f16.f16.f32 "
            "{%0,%1,%2,%3}, {%4,%5,%6,%7}, {%8,%9}, {%0,%1,%2,%3};"
            : "+f"(d[0]), "+f"(d[1]), "+f"(d[2]), "+f"(d[3])
            : "r"(a[0]), "r"(a[1]), "r"(a[2]), "r"(a[3]), "r"(b0), "r"(b1));
    else
        asm volatile(
            "mma.sync.aligned.m16n8k16.row.col.f32.bf16.bf16.f32 "
            "{%0,%1,%2,%3}, {%4,%5,%6,%7}, {%8,%9}, {%0,%1,%2,%3};"
            : "+f"(d[0]), "+f"(d[1]), "+f"(d[2]), "+f"(d[3])
            : "r"(a[0]), "r"(a[1]), "r"(a[2]), "r"(a[3]), "r"(b0), "r"(b1));
}
__device__ __forceinline__ void ldsm4(uint32_t* r, uint32_t addr) {
    asm volatile("ldmatrix.sync.aligned.m8n8.x4.shared.b16 {%0,%1,%2,%3}, [%4];"
                 : "=r"(r[0]), "=r"(r[1]), "=r"(r[2]), "=r"(r[3]) : "r"(addr));
}
__device__ __forceinline__ void cpa16(uint32_t saddr, const void* g) {
    asm volatile("cp.async.ca.shared.global [%0], [%1], 16;" :: "r"(saddr), "l"(g));
}
__device__ __forceinline__ void cpa_commit() { asm volatile("cp.async.commit_group;" ::: "memory"); }
template<int N> __device__ __forceinline__ void cpa_wait() {
    asm volatile("cp.async.wait_group %0;" :: "n"(N) : "memory");
}
__device__ __forceinline__ uint32_t smem_u32(const void* p) {
    uint32_t a;
    asm("{ .reg .u64 t; cvta.to.shared.u64 t, %1; cvt.u32.u64 %0, t; }" : "=r"(a) : "l"(p));
    return a;
}
// grid-wide barrier (R15-validated)
__device__ __forceinline__ void grid_bar(int target) {
    __threadfence();
    __syncthreads();
    if (threadIdx.x == 0) {
        atomicAdd(&g_bar, 1);
        while (atomicAdd(&g_bar, 0) < target) __nanosleep(64);
    }
    __syncthreads();
    __threadfence();
}

// ---------------- GEMM body: Out[128,128] = A[128,K] @ B[128,K]^T -------------------------
// FIN=false (bf16 step): virtual 3 segs of SEGC chunks -> A hi,hi,lo / B hi,lo,hi
// FIN=true  (fp16 fin):  virtual 2 segs: ac=vc, bc=vc&(SEGC-1)
template<int SEGC, bool BIAS, bool FIN>
__device__ __forceinline__ void gemm_cp(const __nv_bfloat16* __restrict__ Ag, long ldA,
                                        const __nv_bfloat16* __restrict__ Bg, long ldB,
                                        int vcBase, int nch,
                                        float* __restrict__ Out, long ldo,
                                        const float* __restrict__ bias) {
    extern __shared__ __align__(16) uint32_t sm[];
    const uint32_t sbase = smem_u32(sm);
    const int tid = threadIdx.x, wid = tid >> 5, lane = tid & 31;
    const int g = lane >> 2, tc = lane & 3;
    const int wr0 = (wid & 3) * 32, wc0 = (wid >> 2) * 32;

    float acc[2][4][4];
#pragma unroll
    for (int f = 0; f < 2; f++)
#pragma unroll
        for (int nf = 0; nf < 4; nf++)
#pragma unroll
            for (int v = 0; v < 4; v++) acc[f][nf][v] = 0.f;

    const int q = lane >> 3, r8 = lane & 7;
    uint32_t aB[2], bB[2];
#pragma unroll
    for (int f = 0; f < 2; f++)
        aB[f] = (uint32_t)(((wr0 + f*16 + r8 + (q & 1)*8)*RSW + (q >> 1)*4) * 4);
#pragma unroll
    for (int n4 = 0; n4 < 2; n4++)
        bB[n4] = (uint32_t)(((128 + wc0 + n4*16 + r8 + (q >> 1)*8)*RSW + (q & 1)*4) * 4);

    const int isB = tid >= 256, lt = tid & 255;
    const int Lr = lt >> 1, offw = (lt & 1)*16;
    const __nv_bfloat16* __restrict__ Gsrc = isB ? Bg : Ag;
    const long ldS = isB ? ldB : ldA;
    const uint32_t dBase = sbase + (uint32_t)(((isB ? 128*RSW : 0) + Lr*RSW + offw) * 4);

    auto load_stage = [&](int c, int s) {
        int vc = vcBase + c;
        int ac, bc;
        if (FIN) {
            ac = vc; bc = vc & (SEGC - 1);
        } else {
            int m = vc & (SEGC - 1);
            ac = (vc < 2*SEGC) ? m : SEGC + m;
            bc = (vc < SEGC) ? vc : ((vc < 2*SEGC) ? SEGC + m : m);
        }
        int ci = isB ? bc : ac;
        const __nv_bfloat16* gp = Gsrc + (long)Lr*ldS + (long)ci*BK + offw*2;
        uint32_t d = dBase + (uint32_t)(s*STG_W*4);
        cpa16(d, gp); cpa16(d + 16, gp + 8);
        cpa16(d + 32, gp + 16); cpa16(d + 48, gp + 24);
        cpa_commit();
    };

    int ls = 0;
#pragma unroll
    for (int p = 0; p < NSTAGE - 1; p++) {
        if (p < nch) load_stage(p, ls); else cpa_commit();
        if (++ls == NSTAGE) ls = 0;
    }

    uint32_t af[2][2][4], bf[2][2][4];

#define LD_FR(kk, buf, stg) do {                                                  \
        uint32_t _kw = (uint32_t)((kk)*32);                                       \
        ldsm4(af[buf][0], (stg) + aB[0] + _kw);                                   \
        ldsm4(af[buf][1], (stg) + aB[1] + _kw);                                   \
        ldsm4(bf[buf][0], (stg) + bB[0] + _kw);                                   \
        ldsm4(bf[buf][1], (stg) + bB[1] + _kw);                                   \
    } while (0)

#define DO_MMA(buf) do {                                                          \
        _Pragma("unroll")                                                         \
        for (int n4 = 0; n4 < 2; n4++) {                                          \
            mma_any<FIN>(acc[0][n4*2],     af[buf][0], bf[buf][n4][0], bf[buf][n4][1]); \
            mma_any<FIN>(acc[1][n4*2],     af[buf][1], bf[buf][n4][0], bf[buf][n4][1]); \
            mma_any<FIN>(acc[0][n4*2 + 1], af[buf][0], bf[buf][n4][2], bf[buf][n4][3]); \
            mma_any<FIN>(acc[1][n4*2 + 1], af[buf][1], bf[buf][n4][2], bf[buf][n4][3]); \
        }                                                                         \
    } while (0)

    int cs = 0;
    for (int ch = 0; ch < nch; ch++) {
        const int rem = nch - 1 - ch;
        if (rem >= 3) cpa_wait<3>();
        else if (rem == 2) cpa_wait<2>();
        else if (rem == 1) cpa_wait<1>();
        else cpa_wait<0>();
        __syncthreads();
        if (ch + NSTAGE - 1 < nch) {
            load_stage(ch + NSTAGE - 1, ls);
            if (++ls == NSTAGE) ls = 0;
        }
        const uint32_t stg = sbase + (uint32_t)(cs*STG_W*4);
        if (++cs == NSTAGE) cs = 0;
        LD_FR(0, 0, stg);
        LD_FR(1, 1, stg);
        DO_MMA(0);
        LD_FR(2, 0, stg);
        DO_MMA(1);
        LD_FR(3, 1, stg);
        DO_MMA(0);
        DO_MMA(1);
    }
#undef LD_FR
#undef DO_MMA
#pragma unroll
    for (int f = 0; f < 2; f++) {
        const int row0 = wr0 + f*16 + g;
#pragma unroll
        for (int nf = 0; nf < 4; nf++) {
            const int col = wc0 + nf*8 + tc*2;
            float2 v0 = make_float2(acc[f][nf][0], acc[f][nf][1]);
            float2 v1 = make_float2(acc[f][nf][2], acc[f][nf][3]);
            if (BIAS) {
                float2 d = *(const float2*)&bias[col];
                v0.x += d.x; v0.y += d.y; v1.x += d.x; v1.y += d.y;
            }
            *(float2*)(Out + (long)row0*ldo + col)       = v0;
            *(float2*)(Out + (long)(row0 + 8)*ldo + col) = v1;
        }
    }
}

// ---------------- persistent step kernel: 9 full steps + cheap final step ----------------
__global__ void __launch_bounds__(512, 1) k_step_all() {
    extern __shared__ __align__(16) uint32_t sm[];
    const int ks = blockIdx.x, mt = blockIdx.y;
    const int lin = mt*KSPLIT + ks;                 // 0..127
    const int tid = threadIdx.x;
    float* slab = (float*)sm;

    int cur = 0, phase = 0;
    for (int s = 0; s < STEPS - 1; s++) {           // steps producing R_1..R_9 (all in S)
        gemm_cp<32, false, false>(g_Text + (size_t)mt*128*KP, KP,
                                  g_Rt[cur], KP,
                                  ks*12, 12,
                                  g_P + ((size_t)ks*NN + mt*128)*DIM, DIM, nullptr);
        grid_bar(++phase * NCTA);

        // distributed reduce: rows [lin*16, lin*16+16); S += ; stage for Rt re-split
        const int row0 = lin*16;
        for (int u = tid; u < 16*DIM; u += 512) {
            int rr = u >> 7, e = u & 127;
            float v = 0.f;
#pragma unroll
            for (int k = 0; k < KSPLIT; k++)
                v += g_P[(size_t)k*NN*DIM + (size_t)(row0 + rr)*DIM + e];
            g_S[(size_t)(row0 + rr)*DIM + e] += v;
            slab[rr*129 + e] = v;
        }
        __syncthreads();
        {
            const int e = tid >> 2, c4 = (tid & 3) * 4;
            __nv_bfloat16* Rt = g_Rt[cur ^ 1];
            uint32_t hw[2], lw[2];
#pragma unroll
            for (int c2 = 0; c2 < 2; c2++) {
                float v0 = slab[(c4 + 2*c2)*129 + e];
                float v1 = slab[(c4 + 2*c2 + 1)*129 + e];
                __nv_bfloat16 h0 = __float2bfloat16(v0);
                __nv_bfloat16 h1 = __float2bfloat16(v1);
                __nv_bfloat162 hh; hh.x = h0; hh.y = h1;
                hw[c2] = *(uint32_t*)&hh;
                __nv_bfloat162 ll;
                ll.x = __float2bfloat16(v0 - __bfloat162float(h0));
                ll.y = __float2bfloat16(v1 - __bfloat162float(h1));
                lw[c2] = *(uint32_t*)&ll;
            }
            *(uint2*)&Rt[(size_t)e*KP + row0 + c4]        = make_uint2(hw[0], hw[1]);
            *(uint2*)&Rt[(size_t)e*KP + 2048 + row0 + c4] = make_uint2(lw[0], lw[1]);
        }
        grid_bar(++phase * NCTA);
        cur ^= 1;
    }

    // FINAL step: only block-0 rows of R_10 are needed (E). 96 CTAs, 1 K-chunk each.
    if (lin < 96) {
        gemm_cp<32, false, false>(g_Text, KP,                // mt = 0 rows
                                  g_Rt[cur], KP,
                                  lin, 1,
                                  g_P + (size_t)lin*128*DIM, DIM, nullptr);
    }
    grid_bar((phase + 1) * NCTA);                            // all 128 arrive

    // reduce 96 partials for row lin -> Rf[lin]
    {
        const int e = tid & 127, kg = tid >> 7;              // 4 k-groups
        float v = 0.f;
        for (int k = kg; k < 96; k += 4)
            v += g_P[(size_t)k*128*DIM + (size_t)lin*DIM + e];
        slab[kg*132 + e] = v;
        __syncthreads();
        if (tid < DIM) {
            float t = slab[tid] + slab[132 + tid] + slab[264 + tid] + slab[396 + tid];
            g_Rf[(size_t)lin*DIM + tid] = t;
        }
    }
}

// final MMA: fp16, virtual K=1024 (2 segs); bias fused
__global__ void __launch_bounds__(512, 1) k_mma_fin(float* __restrict__ out) {
    const int qt = blockIdx.x, bt = blockIdx.y;
    gemm_cp<8, true, true>((const __nv_bfloat16*)(g_Ifin + (size_t)bt*128*1024), 1024,
                           (const __nv_bfloat16*)(g_Gfin + (size_t)qt*128*512), 512,
                           0, 16,
                           out + (size_t)bt*128*OUTC + qt*128, OUTC, g_dvec + qt*128);
}

// ---------------- prep kernels ----------------

__global__ void k_prep(const float* __restrict__ life, const float* __restrict__ bl) {
    int j = blockIdx.x, g = threadIdx.x;
    float s = 0.f;
#pragma unroll
    for (int i = 0; i < NUM; i++) {
        float gt = fmaxf(life[i*NUM + j], 0.f);
        s += gt * bl[(i*NUM + j)*DIM + g];
    }
    g_beta[j*DIM + g] = s;
}

// T phys [Thi|Tlo] of gate*W
__global__ void k_make_T(const float* __restrict__ W, const float* __restrict__ life) {
    const int j = blockIdx.x, i = blockIdx.y;
    const float gate = fmaxf(life[i*NUM + j], 0.f);
    const float* __restrict__ Wb = W + (size_t)(i*NUM + j)*DIM*DIM;   // [g][f]
    __shared__ float sm[32][DIM + 1];
    const int tid = threadIdx.x;
    for (int g0 = 0; g0 < DIM; g0 += 32) {
        for (int u = tid; u < 32*DIM; u += 256) {
            int gg = u >> 7, f = u & 127;
            sm[gg][f] = Wb[(size_t)(g0 + gg)*DIM + f];
        }
        __syncthreads();
#pragma unroll
        for (int it = 0; it < 8; it++) {
            int pi = it*256 + tid;
            int f = pi >> 4, gp = (pi & 15) * 2;
            float x0 = gate * sm[gp][f];
            float x1 = gate * sm[gp + 1][f];
            __nv_bfloat16 h0 = __float2bfloat16(x0);
            __nv_bfloat16 h1 = __float2bfloat16(x1);
            __nv_bfloat162 hv; hv.x = h0; hv.y = h1;
            __nv_bfloat162 lv;
            lv.x = __float2bfloat16(x0 - __bfloat162float(h0));
            lv.y = __float2bfloat16(x1 - __bfloat162float(h1));
            size_t row = (size_t)(i*DIM + f)*KP;
            int col = j*DIM + g0 + gp;
            *(__nv_bfloat162*)&g_Text[row + col]        = hv;
            *(__nv_bfloat162*)&g_Text[row + 2048 + col] = lv;
        }
        __syncthreads();
    }
}

// Rt[0] phys: [Rhi identity | Rlo = 0]; S = R_0; zero grid barrier
__global__ void k_initRS() {
    int r = blockIdx.x, e = threadIdx.x;     // grid 2048 x 128
    g_S[(size_t)r*DIM + e] = (r == (NN - DIM) + e) ? 1.f : 0.f;
    if (r == 0 && e == 0) g_bar = 0;
    if (r < DIM) {
#pragma unroll
        for (int it = 0; it < 16; it++) {
            int cp = (it*128 + e) * 2;       // col pair over KP=4096
            float v0 = (cp < 2048 && cp     == (NN - DIM) + r) ? 1.f : 0.f;
            float v1 = (cp < 2048 && cp + 1 == (NN - DIM) + r) ? 1.f : 0.f;
            __nv_bfloat162 v; v.x = __float2bfloat16(v0); v.y = __float2bfloat16(v1);
            *(__nv_bfloat162*)&g_Rt[0][(size_t)r*KP + cp] = v;
        }
    }
}

// ---------------- merged combine kernels ----------------
__global__ void k_combo1(const float* __restrict__ Wpost, const float* __restrict__ bpre) {
    const int tid = threadIdx.x;                       // 512
    if (blockIdx.x < DIM) {
        int e = blockIdx.x;
        g_WpostT[e*OUTC + tid] = Wpost[(size_t)tid*DIM + e];
    } else {
        int e = blockIdx.x - DIM;
        float s = 0.f;
        for (int r = tid; r < NN; r += 512) s += g_beta[r] * g_S[(size_t)r*DIM + e];
        if (tid < DIM) s += bpre[tid] * g_Rf[(size_t)tid*DIM + e];
        __shared__ float red[512];
        red[tid] = s;
        __syncthreads();
        for (int off = 256; off > 0; off >>= 1) {
            if (tid < off) red[tid] += red[tid + off];
            __syncthreads();
        }
        if (tid == 0) g_h[e] = red[0];
    }
}

__global__ void k_combo2(const float* __restrict__ bpost) {
    const int tid = threadIdx.x;                       // 128
    if (blockIdx.x < 512) {
        int d = blockIdx.x >> 2;
        int q = (blockIdx.x & 3)*128 + tid;
        const float* __restrict__ Er = g_Rf + (size_t)d*DIM;
        float acc = 0.f;
#pragma unroll 8
        for (int e = 0; e < DIM; e++) acc += Er[e] * g_WpostT[e*OUTC + q];
        g_T1[d*OUTC + q] = acc;
    } else {
        int q = (blockIdx.x - 512)*128 + tid;
        float acc = bpost[q];
#pragma unroll 8
        for (int e = 0; e < DIM; e++) acc += g_h[e] * g_WpostT[e*OUTC + q];
        g_dvec[q] = acc;
    }
}

__global__ void k_G(const float* __restrict__ Wpre) {
    int p = blockIdx.y;
    int q = blockIdx.x*128 + threadIdx.x;
    float acc = 0.f;
#pragma unroll 8
    for (int d = 0; d < DIM; d++) acc += Wpre[d*INC + p] * g_T1[d*OUTC + q];
    g_G[p*OUTC + q] = acc;
}

// inp -> fp16 phys [Ihi|Ilo]
__global__ void k_split_inp(const float* __restrict__ inp) {
    int b = blockIdx.x, tid = threadIdx.x;
#pragma unroll
    for (int it = 0; it < 2; it++) {
        int qp = (it*128 + tid) * 2;
        float2 x = *(const float2*)&inp[(size_t)b*INC + qp];
        __half h0 = __float2half_rn(x.x);
        __half h1 = __float2half_rn(x.y);
        __half l0 = __float2half_rn(x.x - __half2float(h0));
        __half l1 = __float2half_rn(x.y - __half2float(h1));
        size_t ro = (size_t)b*1024;
        *(__half2*)&g_Ifin[ro + qp]       = __halves2half2(h0, h1);
        *(__half2*)&g_Ifin[ro + 512 + qp] = __halves2half2(l0, l1);
    }
}

// Gfin row q over p: fp16(G[p][q])
__global__ void k_split_G() {
    int q = blockIdx.x;
    for (int p = threadIdx.x; p < INC; p += 128)
        g_Gfin[(size_t)q*512 + p] = __float2half_rn(g_G[(size_t)p*OUTC + q]);
}

// ---------------- launch ----------------
extern "C" void kernel_launch(void* const* d_in, const int* in_sizes, int n_in,
                              void* d_out, int out_size) {
    (void)in_sizes; (void)n_in; (void)out_size;
    const float* inp   = (const float*)d_in[0];
    const float* Wpre  = (const float*)d_in[1];
    const float* bpre  = (const float*)d_in[2];
    const float* W     = (const float*)d_in[3];
    const float* bl    = (const float*)d_in[4];
    const float* life  = (const float*)d_in[5];
    const float* Wpost = (const float*)d_in[6];
    const float* bpost = (const float*)d_in[7];
    float* out = (float*)d_out;

    cudaFuncSetAttribute(k_step_all, cudaFuncAttributeMaxDynamicSharedMemorySize, SMEM_BYTES);
    cudaFuncSetAttribute(k_mma_fin,  cudaFuncAttributeMaxDynamicSharedMemorySize, SMEM_BYTES);

    k_make_T<<<dim3(NUM, NUM), 256>>>(W, life);          // idx 0
    k_initRS<<<NN, DIM>>>();                             // idx 1
    k_prep<<<NUM, DIM>>>(life, bl);                      // idx 2

    k_step_all<<<dim3(KSPLIT, NUM), 512, SMEM_BYTES>>>();   // idx 3 — all 10 steps

    k_combo1<<<2*DIM, 512>>>(Wpost, bpre);
    k_combo2<<<516, 128>>>(bpost);
    k_G<<<dim3(OUTC/128, INC), 128>>>(Wpre);
    k_split_inp<<<BATCH, 128>>>(inp);
    k_split_G<<<OUTC, 128>>>();
    k_mma_fin<<<dim3(OUTC/128, BATCH/128), 512, SMEM_BYTES>>>(out);
}